// round 1
// baseline (speedup 1.0000x reference)
#include <cuda_runtime.h>
#include <math.h>
#include <cstddef>

// Problem constants
#define B_   4
#define L_   2048
#define D_   1024
#define H_   16
#define DK_  64
#define DV_  64

// ---------------------------------------------------------------------------
// Scratch (allocation-free: __device__ globals)
// ---------------------------------------------------------------------------
static __device__ float g_qh [(size_t)B_ * L_ * D_];          // (b, l, h*dk)
static __device__ float g_kh [(size_t)B_ * L_ * D_];
static __device__ float g_vh [(size_t)B_ * L_ * D_];
static __device__ float g_ctx[(size_t)B_ * L_ * D_];          // (b, l, h*dv)
static __device__ float g_x  [(size_t)B_ * L_ * D_];          // pre-LN
static __device__ float g_scores[(size_t)B_ * H_ * L_ * L_];  // fallback if attn not in d_out

// ---------------------------------------------------------------------------
// Generic fp32 GEMM: C[M,N] = A[M,K] @ W[K,N] + bias[N] (+ residual[M,N])
// M,N multiples of 128; K multiple of 16. 256 threads, 128x128 tile, 8x8/thr.
// ---------------------------------------------------------------------------
__global__ __launch_bounds__(256) void sgemm_bias(
    const float* __restrict__ A, const float* __restrict__ W,
    const float* __restrict__ bias, const float* __restrict__ R,
    float* __restrict__ C, int M, int N, int K)
{
    __shared__ float As[16][128];   // transposed: As[k][m]
    __shared__ float Ws[16][128];   // Ws[k][n]
    const int tid = threadIdx.x;
    const int tx  = tid & 15;
    const int ty  = tid >> 4;
    const int bm  = blockIdx.y * 128;
    const int bn  = blockIdx.x * 128;

    float acc[8][8];
#pragma unroll
    for (int i = 0; i < 8; i++)
#pragma unroll
        for (int j = 0; j < 8; j++) acc[i][j] = 0.0f;

    for (int kt = 0; kt < K; kt += 16) {
#pragma unroll
        for (int u = 0; u < 2; u++) {
            int f   = tid + u * 256;              // 0..511
            int row = f >> 2;                     // 0..127
            int kc  = (f & 3) << 2;               // 0,4,8,12
            float4 av = *(const float4*)(A + (size_t)(bm + row) * K + kt + kc);
            As[kc + 0][row] = av.x; As[kc + 1][row] = av.y;
            As[kc + 2][row] = av.z; As[kc + 3][row] = av.w;
            int wrow = f >> 5;                    // 0..15
            int wc   = (f & 31) << 2;             // 0..124
            *(float4*)&Ws[wrow][wc] = *(const float4*)(W + (size_t)(kt + wrow) * N + bn + wc);
        }
        __syncthreads();
#pragma unroll
        for (int kk = 0; kk < 16; kk++) {
            float a[8], w[8];
#pragma unroll
            for (int i = 0; i < 2; i++) *(float4*)&a[i * 4] = *(const float4*)&As[kk][ty * 8 + i * 4];
#pragma unroll
            for (int j = 0; j < 2; j++) *(float4*)&w[j * 4] = *(const float4*)&Ws[kk][tx * 8 + j * 4];
#pragma unroll
            for (int i = 0; i < 8; i++)
#pragma unroll
                for (int j = 0; j < 8; j++) acc[i][j] = fmaf(a[i], w[j], acc[i][j]);
        }
        __syncthreads();
    }

#pragma unroll
    for (int i = 0; i < 8; i++) {
        int row = bm + ty * 8 + i;
#pragma unroll
        for (int j = 0; j < 2; j++) {
            int col = bn + tx * 8 + j * 4;
            float4 v;
            v.x = acc[i][j * 4 + 0] + bias[col + 0];
            v.y = acc[i][j * 4 + 1] + bias[col + 1];
            v.z = acc[i][j * 4 + 2] + bias[col + 2];
            v.w = acc[i][j * 4 + 3] + bias[col + 3];
            if (R) {
                float4 r = *(const float4*)(R + (size_t)row * N + col);
                v.x += r.x; v.y += r.y; v.z += r.z; v.w += r.w;
            }
            *(float4*)(C + (size_t)row * N + col) = v;
        }
    }
}

// ---------------------------------------------------------------------------
// Scores: S[b,h,q,k] = (qh[b,q,h,:] . kh[b,k,h,:]) / sqrt(DK), masked.
// Block: 128 q  x 64 k, full DK=64 reduction. 256 threads, 8x4/thr.
// Dynamic smem: Qs[128][65] + Ks[64][65].
// ---------------------------------------------------------------------------
__global__ __launch_bounds__(256) void scores_kernel(
    const float* __restrict__ qh, const float* __restrict__ kh,
    const unsigned char* __restrict__ mask, float* __restrict__ S)
{
    extern __shared__ float sm[];
    float (*Qs)[65] = (float (*)[65])sm;               // [128][65]
    float (*Ks)[65] = (float (*)[65])(sm + 128 * 65);  // [64][65]

    const int bh = blockIdx.z;
    const int b  = bh >> 4;
    const int h  = bh & 15;
    const int q0 = blockIdx.y * 128;
    const int k0 = blockIdx.x * 64;
    const int tid = threadIdx.x;

    const float* qb = qh + ((size_t)b * L_ + q0) * D_ + h * DK_;
    const float* kb = kh + ((size_t)b * L_ + k0) * D_ + h * DK_;

#pragma unroll
    for (int u = 0; u < 8; u++) {
        int f = tid + u * 256;           // 0..2047
        int row = f >> 4;
        int c = (f & 15) << 2;
        float4 t = *(const float4*)(qb + (size_t)row * D_ + c);
        Qs[row][c] = t.x; Qs[row][c + 1] = t.y; Qs[row][c + 2] = t.z; Qs[row][c + 3] = t.w;
    }
#pragma unroll
    for (int u = 0; u < 4; u++) {
        int f = tid + u * 256;           // 0..1023
        int row = f >> 4;
        int c = (f & 15) << 2;
        float4 t = *(const float4*)(kb + (size_t)row * D_ + c);
        Ks[row][c] = t.x; Ks[row][c + 1] = t.y; Ks[row][c + 2] = t.z; Ks[row][c + 3] = t.w;
    }
    __syncthreads();

    const int tx = tid & 15, ty = tid >> 4;
    float acc[8][4];
#pragma unroll
    for (int i = 0; i < 8; i++)
#pragma unroll
        for (int j = 0; j < 4; j++) acc[i][j] = 0.0f;

#pragma unroll
    for (int d = 0; d < 64; d++) {
        float a[8], w[4];
#pragma unroll
        for (int i = 0; i < 8; i++) a[i] = Qs[ty * 8 + i][d];
#pragma unroll
        for (int j = 0; j < 4; j++) w[j] = Ks[tx * 4 + j][d];
#pragma unroll
        for (int i = 0; i < 8; i++)
#pragma unroll
            for (int j = 0; j < 4; j++) acc[i][j] = fmaf(a[i], w[j], acc[i][j]);
    }

    const float scale = 0.125f;   // 1/sqrt(64)
#pragma unroll
    for (int i = 0; i < 8; i++) {
        int q = q0 + ty * 8 + i;
        int k = k0 + tx * 4;
        const unsigned char* mrow = mask + ((size_t)b * L_ + q) * L_ + k;
        float4 o;
        o.x = mrow[0] ? -INFINITY : acc[i][0] * scale;
        o.y = mrow[1] ? -INFINITY : acc[i][1] * scale;
        o.z = mrow[2] ? -INFINITY : acc[i][2] * scale;
        o.w = mrow[3] ? -INFINITY : acc[i][3] * scale;
        *(float4*)(S + ((size_t)bh * L_ + q) * L_ + k) = o;
    }
}

// ---------------------------------------------------------------------------
// Row softmax over L_=2048 keys, in place. One block (256 thr) per row.
// ---------------------------------------------------------------------------
__device__ __forceinline__ float warp_max(float v) {
#pragma unroll
    for (int o = 16; o; o >>= 1) v = fmaxf(v, __shfl_xor_sync(0xffffffffu, v, o));
    return v;
}
__device__ __forceinline__ float warp_sum(float v) {
#pragma unroll
    for (int o = 16; o; o >>= 1) v += __shfl_xor_sync(0xffffffffu, v, o);
    return v;
}

__global__ __launch_bounds__(256) void softmax_kernel(float* __restrict__ S)
{
    float* row = S + (size_t)blockIdx.x * L_;
    const int tid = threadIdx.x;
    __shared__ float red[8];

    float x[8];
    *(float4*)&x[0] = *(const float4*)(row + tid * 4);
    *(float4*)&x[4] = *(const float4*)(row + 1024 + tid * 4);

    float m = x[0];
#pragma unroll
    for (int i = 1; i < 8; i++) m = fmaxf(m, x[i]);
    m = warp_max(m);
    if ((tid & 31) == 0) red[tid >> 5] = m;
    __syncthreads();
    float bm = red[0];
#pragma unroll
    for (int w = 1; w < 8; w++) bm = fmaxf(bm, red[w]);
    __syncthreads();

    float s = 0.0f;
#pragma unroll
    for (int i = 0; i < 8; i++) { x[i] = expf(x[i] - bm); s += x[i]; }
    s = warp_sum(s);
    if ((tid & 31) == 0) red[tid >> 5] = s;
    __syncthreads();
    float bs = 0.0f;
#pragma unroll
    for (int w = 0; w < 8; w++) bs += red[w];
    float inv = 1.0f / bs;

#pragma unroll
    for (int i = 0; i < 8; i++) x[i] *= inv;
    *(float4*)(row + tid * 4)        = *(float4*)&x[0];
    *(float4*)(row + 1024 + tid * 4) = *(float4*)&x[4];
}

// ---------------------------------------------------------------------------
// Attn @ V: ctx[b,q,h,:] = sum_k P[b,h,q,k] * vh[b,k,h,:]
// Block: 128 q x 64 dv, K-chunks of 64. 256 threads, 8x4/thr.
// ---------------------------------------------------------------------------
__global__ __launch_bounds__(256) void av_kernel(
    const float* __restrict__ P, const float* __restrict__ vh, float* __restrict__ ctx)
{
    extern __shared__ float sm[];
    float (*Ps)[65] = (float (*)[65])sm;               // [128][65] (q x kchunk)
    float (*Vs)[65] = (float (*)[65])(sm + 128 * 65);  // [64][65]  (kchunk x dv)

    const int bh = blockIdx.z;
    const int b  = bh >> 4;
    const int h  = bh & 15;
    const int q0 = blockIdx.x * 128;
    const int tid = threadIdx.x;
    const int tx = tid & 15, ty = tid >> 4;

    float acc[8][4];
#pragma unroll
    for (int i = 0; i < 8; i++)
#pragma unroll
        for (int j = 0; j < 4; j++) acc[i][j] = 0.0f;

    for (int k0 = 0; k0 < L_; k0 += 64) {
#pragma unroll
        for (int u = 0; u < 8; u++) {
            int f = tid + u * 256;
            int row = f >> 4;
            int c = (f & 15) << 2;
            float4 t = *(const float4*)(P + ((size_t)bh * L_ + q0 + row) * L_ + k0 + c);
            Ps[row][c] = t.x; Ps[row][c + 1] = t.y; Ps[row][c + 2] = t.z; Ps[row][c + 3] = t.w;
        }
#pragma unroll
        for (int u = 0; u < 4; u++) {
            int f = tid + u * 256;
            int row = f >> 4;
            int c = (f & 15) << 2;
            float4 t = *(const float4*)(vh + ((size_t)b * L_ + k0 + row) * D_ + h * DV_ + c);
            Vs[row][c] = t.x; Vs[row][c + 1] = t.y; Vs[row][c + 2] = t.z; Vs[row][c + 3] = t.w;
        }
        __syncthreads();
#pragma unroll
        for (int kk = 0; kk < 64; kk++) {
            float a[8], w[4];
#pragma unroll
            for (int i = 0; i < 8; i++) a[i] = Ps[ty * 8 + i][kk];
#pragma unroll
            for (int j = 0; j < 4; j++) w[j] = Vs[kk][tx * 4 + j];
#pragma unroll
            for (int i = 0; i < 8; i++)
#pragma unroll
                for (int j = 0; j < 4; j++) acc[i][j] = fmaf(a[i], w[j], acc[i][j]);
        }
        __syncthreads();
    }

#pragma unroll
    for (int i = 0; i < 8; i++) {
        int q = q0 + ty * 8 + i;
        float4 o;
        o.x = acc[i][0]; o.y = acc[i][1]; o.z = acc[i][2]; o.w = acc[i][3];
        *(float4*)(ctx + ((size_t)b * L_ + q) * D_ + h * DV_ + tx * 4) = o;
    }
}

// ---------------------------------------------------------------------------
// LayerNorm over D_=1024: out = (x - mu) / sqrt(var + eps) * gamma + beta
// One block (256 thr) per row, 4 elems / thread.
// ---------------------------------------------------------------------------
__global__ __launch_bounds__(256) void ln_kernel(
    const float* __restrict__ X, const float* __restrict__ gamma,
    const float* __restrict__ beta, float* __restrict__ O)
{
    const float* x = X + (size_t)blockIdx.x * D_;
    const int tid = threadIdx.x;
    __shared__ float rs[8], rq[8];

    float4 v = *(const float4*)(x + tid * 4);
    float s  = v.x + v.y + v.z + v.w;
    float q2 = v.x * v.x + v.y * v.y + v.z * v.z + v.w * v.w;
    s  = warp_sum(s);
    q2 = warp_sum(q2);
    if ((tid & 31) == 0) { rs[tid >> 5] = s; rq[tid >> 5] = q2; }
    __syncthreads();
    float S = 0.0f, Q = 0.0f;
#pragma unroll
    for (int w = 0; w < 8; w++) { S += rs[w]; Q += rq[w]; }
    float mu  = S * (1.0f / D_);
    float var = Q * (1.0f / D_) - mu * mu;
    float inv = rsqrtf(var + 1e-5f);

    float4 g = *(const float4*)(gamma + tid * 4);
    float4 bb = *(const float4*)(beta + tid * 4);
    float4 o;
    o.x = (v.x - mu) * inv * g.x + bb.x;
    o.y = (v.y - mu) * inv * g.y + bb.y;
    o.z = (v.z - mu) * inv * g.z + bb.z;
    o.w = (v.w - mu) * inv * g.w + bb.w;
    *(float4*)(O + (size_t)blockIdx.x * D_ + tid * 4) = o;
}

// ---------------------------------------------------------------------------
// Launch
// ---------------------------------------------------------------------------
extern "C" void kernel_launch(void* const* d_in, const int* in_sizes, int n_in,
                              void* d_out, int out_size)
{
    const float*         q     = (const float*)d_in[0];
    const float*         k     = (const float*)d_in[1];
    const float*         v     = (const float*)d_in[2];
    /* d_in[3] = c (unused) */
    const unsigned char* mask  = (const unsigned char*)d_in[4];
    const float*         Wq    = (const float*)d_in[5];
    const float*         bq    = (const float*)d_in[6];
    const float*         Wk    = (const float*)d_in[7];
    const float*         bk    = (const float*)d_in[8];
    const float*         Wv    = (const float*)d_in[9];
    const float*         bv    = (const float*)d_in[10];
    const float*         Wo    = (const float*)d_in[11];
    const float*         bo    = (const float*)d_in[12];
    const float*         gamma = (const float*)d_in[13];
    const float*         beta  = (const float*)d_in[14];
    float*               out   = (float*)d_out;

    float *qh, *kh, *vh, *ctx, *xb, *sc;
    cudaGetSymbolAddress((void**)&qh,  g_qh);
    cudaGetSymbolAddress((void**)&kh,  g_kh);
    cudaGetSymbolAddress((void**)&vh,  g_vh);
    cudaGetSymbolAddress((void**)&ctx, g_ctx);
    cudaGetSymbolAddress((void**)&xb,  g_x);
    cudaGetSymbolAddress((void**)&sc,  g_scores);

    const size_t n_out  = (size_t)B_ * L_ * D_;            // 8,388,608
    const size_t n_attn = (size_t)B_ * H_ * L_ * L_;       // 268,435,456
    float* attn = ((size_t)out_size >= n_out + n_attn) ? out + n_out : sc;

    const int SMEM_BIG = (128 * 65 + 64 * 65) * (int)sizeof(float);  // 49,920 B
    cudaFuncSetAttribute(scores_kernel, cudaFuncAttributeMaxDynamicSharedMemorySize, SMEM_BIG);
    cudaFuncSetAttribute(av_kernel,     cudaFuncAttributeMaxDynamicSharedMemorySize, SMEM_BIG);

    const int M = B_ * L_;                 // 8192
    dim3 gproj(D_ / 128, M / 128);         // (8, 64)

    sgemm_bias<<<gproj, 256>>>(q, Wq, bq, nullptr, qh, M, D_, D_);
    sgemm_bias<<<gproj, 256>>>(k, Wk, bk, nullptr, kh, M, D_, D_);
    sgemm_bias<<<gproj, 256>>>(v, Wv, bv, nullptr, vh, M, D_, D_);

    scores_kernel<<<dim3(L_ / 64, L_ / 128, B_ * H_), 256, SMEM_BIG>>>(qh, kh, mask, attn);
    softmax_kernel<<<B_ * H_ * L_, 256>>>(attn);
    av_kernel<<<dim3(L_ / 128, 1, B_ * H_), 256, SMEM_BIG>>>(attn, vh, ctx);

    sgemm_bias<<<gproj, 256>>>(ctx, Wo, bo, q, xb, M, D_, D_);
    ln_kernel<<<M, 256>>>(xb, gamma, beta, out);
}

// round 2
// speedup vs baseline: 2.0555x; 2.0555x over previous
#include <cuda_runtime.h>
#include <math.h>
#include <cstddef>
#include <stdint.h>

#define B_   4
#define L_   2048
#define D_   1024
#define H_   16
#define DKV  64

// ---------------------------------------------------------------------------
// Scratch (allocation-free: __device__ globals)
// ---------------------------------------------------------------------------
static __device__ float g_qh [(size_t)B_ * L_ * D_];
static __device__ float g_kh [(size_t)B_ * L_ * D_];
static __device__ float g_vh [(size_t)B_ * L_ * D_];
static __device__ float g_ctx[(size_t)B_ * L_ * D_];
static __device__ float g_x  [(size_t)B_ * L_ * D_];

// ---------------------------------------------------------------------------
// tf32 helpers
// ---------------------------------------------------------------------------
__device__ __forceinline__ uint32_t f2tf(float f) {
    uint32_t u;
    asm("cvt.rna.tf32.f32 %0, %1;" : "=r"(u) : "f"(f));
    return u;
}

// D += A(16x8, row) * B(8x8, col), tf32 in, f32 acc.
__device__ __forceinline__ void mma8(float4& d,
    uint32_t a0, uint32_t a1, uint32_t a2, uint32_t a3,
    uint32_t b0, uint32_t b1)
{
    asm volatile(
        "mma.sync.aligned.m16n8k8.row.col.f32.tf32.tf32.f32 "
        "{%0,%1,%2,%3}, {%4,%5,%6,%7}, {%8,%9}, {%0,%1,%2,%3};"
        : "+f"(d.x), "+f"(d.y), "+f"(d.z), "+f"(d.w)
        : "r"(a0), "r"(a1), "r"(a2), "r"(a3), "r"(b0), "r"(b1));
}

// ---------------------------------------------------------------------------
// Projection GEMM: C[M,N] = A[M,K] @ W[K,N] + bias (+ residual)
// 128x128 block tile, 8 warps as 4(m) x 2(n), warp tile 32x64, k-step 32.
// ---------------------------------------------------------------------------
__global__ __launch_bounds__(256) void gemm_tf32(
    const float* __restrict__ A, const float* __restrict__ W,
    const float* __restrict__ bias, const float* __restrict__ R,
    float* __restrict__ C, int M, int N, int K)
{
    __shared__ uint32_t As[128][36];    // [m][k], pad 36 -> frag banks 4g+c
    __shared__ uint32_t Ws[32][136];    // [k][n], pad 136 -> frag banks 8c+g
    const int tid  = threadIdx.x;
    const int lane = tid & 31, wid = tid >> 5;
    const int wm = (wid & 3) * 32, wn = (wid >> 2) * 64;
    const int g = lane >> 2, c = lane & 3;
    const int bm = blockIdx.y * 128, bn = blockIdx.x * 128;

    float4 acc[2][8];
#pragma unroll
    for (int mi = 0; mi < 2; mi++)
#pragma unroll
        for (int j = 0; j < 8; j++) acc[mi][j] = make_float4(0.f, 0.f, 0.f, 0.f);

    for (int kt = 0; kt < K; kt += 32) {
        __syncthreads();
#pragma unroll
        for (int u = 0; u < 4; u++) {
            int i = tid + u * 256;
            int r = i >> 3, kc = (i & 7) << 2;
            float4 t = *(const float4*)(A + (size_t)(bm + r) * K + kt + kc);
            uint4 s = { f2tf(t.x), f2tf(t.y), f2tf(t.z), f2tf(t.w) };
            *(uint4*)&As[r][kc] = s;
        }
#pragma unroll
        for (int u = 0; u < 4; u++) {
            int i = tid + u * 256;
            int r = i >> 5, nc = (i & 31) << 2;
            float4 t = *(const float4*)(W + (size_t)(kt + r) * N + bn + nc);
            uint4 s = { f2tf(t.x), f2tf(t.y), f2tf(t.z), f2tf(t.w) };
            *(uint4*)&Ws[r][nc] = s;
        }
        __syncthreads();

#pragma unroll
        for (int kk = 0; kk < 32; kk += 8) {
            uint32_t a[2][4];
#pragma unroll
            for (int mi = 0; mi < 2; mi++) {
                int r = wm + mi * 16;
                a[mi][0] = As[r + g    ][kk + c];
                a[mi][1] = As[r + g + 8][kk + c];
                a[mi][2] = As[r + g    ][kk + c + 4];
                a[mi][3] = As[r + g + 8][kk + c + 4];
            }
#pragma unroll
            for (int j = 0; j < 8; j++) {
                uint32_t b0 = Ws[kk + c    ][wn + j * 8 + g];
                uint32_t b1 = Ws[kk + c + 4][wn + j * 8 + g];
                mma8(acc[0][j], a[0][0], a[0][1], a[0][2], a[0][3], b0, b1);
                mma8(acc[1][j], a[1][0], a[1][1], a[1][2], a[1][3], b0, b1);
            }
        }
    }

#pragma unroll
    for (int mi = 0; mi < 2; mi++) {
#pragma unroll
        for (int j = 0; j < 8; j++) {
            int r0  = bm + wm + mi * 16 + g;
            int col = bn + wn + j * 8 + (c << 1);
            float bx = bias[col], by = bias[col + 1];
            float2 v0 = { acc[mi][j].x + bx, acc[mi][j].y + by };
            float2 v1 = { acc[mi][j].z + bx, acc[mi][j].w + by };
            if (R) {
                float2 r0v = *(const float2*)(R + (size_t)r0 * N + col);
                float2 r1v = *(const float2*)(R + (size_t)(r0 + 8) * N + col);
                v0.x += r0v.x; v0.y += r0v.y;
                v1.x += r1v.x; v1.y += r1v.y;
            }
            *(float2*)(C + (size_t)r0 * N + col)       = v0;
            *(float2*)(C + (size_t)(r0 + 8) * N + col) = v1;
        }
    }
}

// ---------------------------------------------------------------------------
// Fused attention: per block = 128 q rows x full key loop (tiles of 64).
// Pass 1: online row max/sum (flash). Pass 2: recompute scores, write
// normalized attn once, accumulate ctx = P @ V in registers.
// 8 warps, each owns 16 q rows across the full 64-wide k/dv tile.
// ---------------------------------------------------------------------------
#define BQ 128
#define BK 64

__global__ __launch_bounds__(256) void attn_kernel(
    const float* __restrict__ qh, const float* __restrict__ kh,
    const float* __restrict__ vh, const unsigned char* __restrict__ mask,
    float* __restrict__ attn, float* __restrict__ ctx, int write_attn)
{
    extern __shared__ uint32_t sm[];
    uint32_t* Qs = sm;                 // [128][68]
    uint32_t* Ks = sm + 128 * 68;      // [64][68]
    uint32_t* Vs = sm + 128 * 68 + 64 * 68;            // [64][72]
    uint32_t* Ps = sm + 128 * 68 + 64 * 68 + 64 * 72;  // [128][68]

    const int tid  = threadIdx.x;
    const int lane = tid & 31, wid = tid >> 5;
    const int g = lane >> 2, c = lane & 3;
    const int q0 = blockIdx.x * BQ;
    const int bh = blockIdx.y, b = bh >> 4, h = bh & 15;
    const int qw = wid * 16;                 // warp's q offset in block
    const float scale = 0.125f;              // 1/sqrt(64)

    // Load Q tile (128 x 64) -> smem as tf32
    const float* qbase = qh + ((size_t)(b * L_ + q0)) * D_ + h * DKV;
#pragma unroll
    for (int u = 0; u < 8; u++) {
        int i = tid + u * 256;
        int r = i >> 4, dc = (i & 15) << 2;
        float4 t = *(const float4*)(qbase + (size_t)r * D_ + dc);
        uint4 s = { f2tf(t.x), f2tf(t.y), f2tf(t.z), f2tf(t.w) };
        *(uint4*)&Qs[r * 68 + dc] = s;
    }

    const int qg0 = q0 + qw + g;
    const int qg1 = qg0 + 8;
    const unsigned char* mbase = mask + (size_t)b * L_ * L_;

    float m0 = -INFINITY, m1 = -INFINITY, l0 = 0.f, l1 = 0.f;

    // ------------------------- PASS 1: stats -------------------------
    for (int kt = 0; kt < L_; kt += BK) {
        __syncthreads();
        const float* kbase = kh + ((size_t)(b * L_ + kt)) * D_ + h * DKV;
#pragma unroll
        for (int u = 0; u < 4; u++) {
            int i = tid + u * 256;
            int r = i >> 4, dc = (i & 15) << 2;
            float4 t = *(const float4*)(kbase + (size_t)r * D_ + dc);
            uint4 s = { f2tf(t.x), f2tf(t.y), f2tf(t.z), f2tf(t.w) };
            *(uint4*)&Ks[r * 68 + dc] = s;
        }
        __syncthreads();

        float4 S[8];
#pragma unroll
        for (int j = 0; j < 8; j++) S[j] = make_float4(0.f, 0.f, 0.f, 0.f);
#pragma unroll
        for (int dd = 0; dd < 64; dd += 8) {
            uint32_t a0 = Qs[(qw + g    ) * 68 + dd + c];
            uint32_t a1 = Qs[(qw + g + 8) * 68 + dd + c];
            uint32_t a2 = Qs[(qw + g    ) * 68 + dd + c + 4];
            uint32_t a3 = Qs[(qw + g + 8) * 68 + dd + c + 4];
#pragma unroll
            for (int j = 0; j < 8; j++) {
                uint32_t b0 = Ks[(j * 8 + g) * 68 + dd + c];
                uint32_t b1 = Ks[(j * 8 + g) * 68 + dd + c + 4];
                mma8(S[j], a0, a1, a2, a3, b0, b1);
            }
        }

        float tm0 = -INFINITY, tm1 = -INFINITY;
#pragma unroll
        for (int j = 0; j < 8; j++) {
            int kcol = kt + j * 8 + (c << 1);
            uchar2 mr0 = *(const uchar2*)(mbase + (size_t)qg0 * L_ + kcol);
            uchar2 mr1 = *(const uchar2*)(mbase + (size_t)qg1 * L_ + kcol);
            S[j].x = mr0.x ? -INFINITY : S[j].x * scale;
            S[j].y = mr0.y ? -INFINITY : S[j].y * scale;
            S[j].z = mr1.x ? -INFINITY : S[j].z * scale;
            S[j].w = mr1.y ? -INFINITY : S[j].w * scale;
            tm0 = fmaxf(tm0, fmaxf(S[j].x, S[j].y));
            tm1 = fmaxf(tm1, fmaxf(S[j].z, S[j].w));
        }
        tm0 = fmaxf(tm0, __shfl_xor_sync(0xffffffffu, tm0, 1));
        tm0 = fmaxf(tm0, __shfl_xor_sync(0xffffffffu, tm0, 2));
        tm1 = fmaxf(tm1, __shfl_xor_sync(0xffffffffu, tm1, 1));
        tm1 = fmaxf(tm1, __shfl_xor_sync(0xffffffffu, tm1, 2));

        float mn0 = fmaxf(m0, tm0), mn1 = fmaxf(m1, tm1);
        float ts0 = 0.f, ts1 = 0.f;
#pragma unroll
        for (int j = 0; j < 8; j++) {
            ts0 += __expf(S[j].x - mn0) + __expf(S[j].y - mn0);
            ts1 += __expf(S[j].z - mn1) + __expf(S[j].w - mn1);
        }
        ts0 += __shfl_xor_sync(0xffffffffu, ts0, 1);
        ts0 += __shfl_xor_sync(0xffffffffu, ts0, 2);
        ts1 += __shfl_xor_sync(0xffffffffu, ts1, 1);
        ts1 += __shfl_xor_sync(0xffffffffu, ts1, 2);

        l0 = l0 * __expf(m0 - mn0) + ts0;
        l1 = l1 * __expf(m1 - mn1) + ts1;
        m0 = mn0; m1 = mn1;
    }

    // ------------------- PASS 2: write attn, accumulate O -------------------
    const float inv0 = 1.0f / l0;
    const float inv1 = 1.0f / l1;
    float4 O[8];
#pragma unroll
    for (int j = 0; j < 8; j++) O[j] = make_float4(0.f, 0.f, 0.f, 0.f);

    for (int kt = 0; kt < L_; kt += BK) {
        __syncthreads();
        const float* kbase = kh + ((size_t)(b * L_ + kt)) * D_ + h * DKV;
        const float* vbase = vh + ((size_t)(b * L_ + kt)) * D_ + h * DKV;
#pragma unroll
        for (int u = 0; u < 4; u++) {
            int i = tid + u * 256;
            int r = i >> 4, dc = (i & 15) << 2;
            float4 t = *(const float4*)(kbase + (size_t)r * D_ + dc);
            uint4 s = { f2tf(t.x), f2tf(t.y), f2tf(t.z), f2tf(t.w) };
            *(uint4*)&Ks[r * 68 + dc] = s;
            float4 tv = *(const float4*)(vbase + (size_t)r * D_ + dc);
            uint4 sv = { f2tf(tv.x), f2tf(tv.y), f2tf(tv.z), f2tf(tv.w) };
            *(uint4*)&Vs[r * 72 + dc] = sv;
        }
        __syncthreads();

        float4 S[8];
#pragma unroll
        for (int j = 0; j < 8; j++) S[j] = make_float4(0.f, 0.f, 0.f, 0.f);
#pragma unroll
        for (int dd = 0; dd < 64; dd += 8) {
            uint32_t a0 = Qs[(qw + g    ) * 68 + dd + c];
            uint32_t a1 = Qs[(qw + g + 8) * 68 + dd + c];
            uint32_t a2 = Qs[(qw + g    ) * 68 + dd + c + 4];
            uint32_t a3 = Qs[(qw + g + 8) * 68 + dd + c + 4];
#pragma unroll
            for (int j = 0; j < 8; j++) {
                uint32_t b0 = Ks[(j * 8 + g) * 68 + dd + c];
                uint32_t b1 = Ks[(j * 8 + g) * 68 + dd + c + 4];
                mma8(S[j], a0, a1, a2, a3, b0, b1);
            }
        }

        // P = exp(s - m) / l, store (tf32) into Ps
#pragma unroll
        for (int j = 0; j < 8; j++) {
            int kcol = kt + j * 8 + (c << 1);
            uchar2 mr0 = *(const uchar2*)(mbase + (size_t)qg0 * L_ + kcol);
            uchar2 mr1 = *(const uchar2*)(mbase + (size_t)qg1 * L_ + kcol);
            float px = mr0.x ? 0.f : __expf(S[j].x * scale - m0) * inv0;
            float py = mr0.y ? 0.f : __expf(S[j].y * scale - m0) * inv0;
            float pz = mr1.x ? 0.f : __expf(S[j].z * scale - m1) * inv1;
            float pw = mr1.y ? 0.f : __expf(S[j].w * scale - m1) * inv1;
            int r0 = (qw + g    ) * 68 + j * 8 + (c << 1);
            int r1 = (qw + g + 8) * 68 + j * 8 + (c << 1);
            Ps[r0]     = f2tf(px);
            Ps[r0 + 1] = f2tf(py);
            Ps[r1]     = f2tf(pz);
            Ps[r1 + 1] = f2tf(pw);
        }
        __syncwarp();

        if (write_attn) {
            float* abase = attn + ((size_t)bh * L_ + q0 + qw) * L_ + kt;
#pragma unroll
            for (int rr = 0; rr < 8; rr++) {
                int r   = rr * 2 + (lane >> 4);      // 0..15
                int col = (lane & 15) << 2;          // 0..60
                float4 t = *(float4*)&Ps[(qw + r) * 68 + col];
                *(float4*)(abase + (size_t)r * L_ + col) = t;
            }
        }

        // O += P @ V
#pragma unroll
        for (int kk = 0; kk < 64; kk += 8) {
            uint32_t a0 = Ps[(qw + g    ) * 68 + kk + c];
            uint32_t a1 = Ps[(qw + g + 8) * 68 + kk + c];
            uint32_t a2 = Ps[(qw + g    ) * 68 + kk + c + 4];
            uint32_t a3 = Ps[(qw + g + 8) * 68 + kk + c + 4];
#pragma unroll
            for (int j = 0; j < 8; j++) {
                uint32_t b0 = Vs[(kk + c    ) * 72 + j * 8 + g];
                uint32_t b1 = Vs[(kk + c + 4) * 72 + j * 8 + g];
                mma8(O[j], a0, a1, a2, a3, b0, b1);
            }
        }
    }

    // write ctx (b, q, h*64 + dv)
    float* cb0 = ctx + ((size_t)(b * L_ + qg0)) * D_ + h * DKV;
    float* cb1 = cb0 + (size_t)8 * D_;
#pragma unroll
    for (int j = 0; j < 8; j++) {
        int col = j * 8 + (c << 1);
        *(float2*)(cb0 + col) = make_float2(O[j].x, O[j].y);
        *(float2*)(cb1 + col) = make_float2(O[j].z, O[j].w);
    }
}

// ---------------------------------------------------------------------------
// LayerNorm over D_=1024
// ---------------------------------------------------------------------------
__device__ __forceinline__ float warp_sum(float v) {
#pragma unroll
    for (int o = 16; o; o >>= 1) v += __shfl_xor_sync(0xffffffffu, v, o);
    return v;
}

__global__ __launch_bounds__(256) void ln_kernel(
    const float* __restrict__ X, const float* __restrict__ gamma,
    const float* __restrict__ beta, float* __restrict__ O)
{
    const float* x = X + (size_t)blockIdx.x * D_;
    const int tid = threadIdx.x;
    __shared__ float rs[8], rq[8];

    float4 v = *(const float4*)(x + tid * 4);
    float s  = v.x + v.y + v.z + v.w;
    float q2 = v.x * v.x + v.y * v.y + v.z * v.z + v.w * v.w;
    s  = warp_sum(s);
    q2 = warp_sum(q2);
    if ((tid & 31) == 0) { rs[tid >> 5] = s; rq[tid >> 5] = q2; }
    __syncthreads();
    float S = 0.f, Q = 0.f;
#pragma unroll
    for (int w = 0; w < 8; w++) { S += rs[w]; Q += rq[w]; }
    float mu  = S * (1.0f / D_);
    float var = Q * (1.0f / D_) - mu * mu;
    float inv = rsqrtf(var + 1e-5f);

    float4 gmm = *(const float4*)(gamma + tid * 4);
    float4 bb  = *(const float4*)(beta + tid * 4);
    float4 o;
    o.x = (v.x - mu) * inv * gmm.x + bb.x;
    o.y = (v.y - mu) * inv * gmm.y + bb.y;
    o.z = (v.z - mu) * inv * gmm.z + bb.z;
    o.w = (v.w - mu) * inv * gmm.w + bb.w;
    *(float4*)(O + (size_t)blockIdx.x * D_ + tid * 4) = o;
}

// ---------------------------------------------------------------------------
// Launch
// ---------------------------------------------------------------------------
extern "C" void kernel_launch(void* const* d_in, const int* in_sizes, int n_in,
                              void* d_out, int out_size)
{
    const float*         q     = (const float*)d_in[0];
    const float*         k     = (const float*)d_in[1];
    const float*         v     = (const float*)d_in[2];
    const unsigned char* mask  = (const unsigned char*)d_in[4];
    const float*         Wq    = (const float*)d_in[5];
    const float*         bq    = (const float*)d_in[6];
    const float*         Wk    = (const float*)d_in[7];
    const float*         bk    = (const float*)d_in[8];
    const float*         Wv    = (const float*)d_in[9];
    const float*         bv    = (const float*)d_in[10];
    const float*         Wo    = (const float*)d_in[11];
    const float*         bo    = (const float*)d_in[12];
    const float*         gamma = (const float*)d_in[13];
    const float*         beta  = (const float*)d_in[14];
    float*               out   = (float*)d_out;

    float *qh, *kh, *vh, *ctx, *xb;
    cudaGetSymbolAddress((void**)&qh,  g_qh);
    cudaGetSymbolAddress((void**)&kh,  g_kh);
    cudaGetSymbolAddress((void**)&vh,  g_vh);
    cudaGetSymbolAddress((void**)&ctx, g_ctx);
    cudaGetSymbolAddress((void**)&xb,  g_x);

    const size_t n_out  = (size_t)B_ * L_ * D_;
    const size_t n_attn = (size_t)B_ * H_ * L_ * L_;
    int write_attn = ((size_t)out_size >= n_out + n_attn) ? 1 : 0;
    float* attn = write_attn ? out + n_out : nullptr;

    const int ATTN_SMEM = (128 * 68 + 64 * 68 + 64 * 72 + 128 * 68) * 4;  // 105472
    cudaFuncSetAttribute(attn_kernel, cudaFuncAttributeMaxDynamicSharedMemorySize, ATTN_SMEM);

    const int M = B_ * L_;                 // 8192
    dim3 gproj(D_ / 128, M / 128);         // (8, 64)

    gemm_tf32<<<gproj, 256>>>(q, Wq, bq, nullptr, qh, M, D_, D_);
    gemm_tf32<<<gproj, 256>>>(k, Wk, bk, nullptr, kh, M, D_, D_);
    gemm_tf32<<<gproj, 256>>>(v, Wv, bv, nullptr, vh, M, D_, D_);

    attn_kernel<<<dim3(L_ / BQ, B_ * H_), 256, ATTN_SMEM>>>(qh, kh, vh, mask, attn, ctx, write_attn);

    gemm_tf32<<<gproj, 256>>>(ctx, Wo, bo, q, xb, M, D_, D_);
    ln_kernel<<<M, 256>>>(xb, gamma, beta, out);
}

// round 4
// speedup vs baseline: 2.1586x; 1.0502x over previous
#include <cuda_runtime.h>
#include <math.h>
#include <cstddef>
#include <stdint.h>

#define B_   4
#define L_   2048
#define D_   1024
#define H_   16
#define DKV  64

// ---------------------------------------------------------------------------
// Scratch (allocation-free: __device__ globals)
// ---------------------------------------------------------------------------
static __device__ float g_qh [(size_t)B_ * L_ * D_];
static __device__ float g_kh [(size_t)B_ * L_ * D_];
static __device__ float g_vh [(size_t)B_ * L_ * D_];
static __device__ float g_ctx[(size_t)B_ * L_ * D_];
static __device__ float g_x  [(size_t)B_ * L_ * D_];
static __device__ float g_wr [4 * 1048576];          // tf32-rounded Wq,Wk,Wv,Wo

// ---------------------------------------------------------------------------
// Helpers
// ---------------------------------------------------------------------------
__device__ __forceinline__ uint32_t f2tf(float f) {
    uint32_t u;
    asm("cvt.rna.tf32.f32 %0, %1;" : "=r"(u) : "f"(f));
    return u;
}
__device__ __forceinline__ float rndf(float x) { return __uint_as_float(f2tf(x)); }

__device__ __forceinline__ void mma8(float4& d,
    uint32_t a0, uint32_t a1, uint32_t a2, uint32_t a3,
    uint32_t b0, uint32_t b1)
{
    asm volatile(
        "mma.sync.aligned.m16n8k8.row.col.f32.tf32.tf32.f32 "
        "{%0,%1,%2,%3}, {%4,%5,%6,%7}, {%8,%9}, {%0,%1,%2,%3};"
        : "+f"(d.x), "+f"(d.y), "+f"(d.z), "+f"(d.w)
        : "r"(a0), "r"(a1), "r"(a2), "r"(a3), "r"(b0), "r"(b1));
}

__device__ __forceinline__ void cp16(uint32_t dst, const void* src) {
    asm volatile("cp.async.ca.shared.global [%0], [%1], 16;" :: "r"(dst), "l"(src));
}

// ---------------------------------------------------------------------------
// Weight pre-rounding (once per launch, 4 x 1M elements)
// ---------------------------------------------------------------------------
__global__ __launch_bounds__(256) void round_kernel(
    const float4* __restrict__ src, float4* __restrict__ dst, int n4)
{
    int i = blockIdx.x * blockDim.x + threadIdx.x;
    if (i < n4) {
        float4 v = src[i];
        v.x = rndf(v.x); v.y = rndf(v.y); v.z = rndf(v.z); v.w = rndf(v.w);
        dst[i] = v;
    }
}

// ---------------------------------------------------------------------------
// GEMM body: C[M=8192, N=1024] = A @ W + bias (+R), tf32, cp.async 2-stage.
// A raw f32 (cvt in frag load, idempotent), W pre-rounded.
// As: [2][128][40] f32, Ws: [2][32][136] f32 (dynamic smem, 75776 B).
// ---------------------------------------------------------------------------
__device__ __forceinline__ void gemm_body(
    const float* __restrict__ A, const float* __restrict__ W,
    const float* __restrict__ bias, const float* __restrict__ R,
    float* __restrict__ C, int round_c, char* smraw)
{
    float* As = (float*)smraw;                 // 2*128*40
    float* Ws = (float*)smraw + 2 * 128 * 40;  // 2*32*136
    const int tid  = threadIdx.x;
    const int lane = tid & 31, wid = tid >> 5;
    const int wm = (wid & 3) * 32, wn = (wid >> 2) * 64;
    const int g = lane >> 2, c = lane & 3;
    const int bm = blockIdx.y * 128, bn = blockIdx.x * 128;
    const int K = D_, N = D_;

    uint32_t asBase = (uint32_t)__cvta_generic_to_shared(As);
    uint32_t wsBase = (uint32_t)__cvta_generic_to_shared(Ws);

    auto issue = [&](int buf, int kt) {
#pragma unroll
        for (int u = 0; u < 4; u++) {
            int i = tid + u * 256;
            int r = i >> 3, off = (i & 7) << 2;
            cp16(asBase + (uint32_t)(buf * 5120 + r * 40 + off) * 4,
                 A + (size_t)(bm + r) * K + kt + off);
        }
#pragma unroll
        for (int u = 0; u < 4; u++) {
            int i = tid + u * 256;
            int r = i >> 5, off = (i & 31) << 2;
            cp16(wsBase + (uint32_t)(buf * 4352 + r * 136 + off) * 4,
                 W + (size_t)(kt + r) * N + bn + off);
        }
        asm volatile("cp.async.commit_group;");
    };

    float4 acc[2][8];
#pragma unroll
    for (int mi = 0; mi < 2; mi++)
#pragma unroll
        for (int j = 0; j < 8; j++) acc[mi][j] = make_float4(0.f, 0.f, 0.f, 0.f);

    issue(0, 0);
    int buf = 0;
    for (int kt = 0; kt < K; kt += 32) {
        if (kt + 32 < K) {
            issue(buf ^ 1, kt + 32);
            asm volatile("cp.async.wait_group 1;");
        } else {
            asm volatile("cp.async.wait_group 0;");
        }
        __syncthreads();
        const float* Ab = As + buf * 5120;
        const float* Wb = Ws + buf * 4352;
#pragma unroll
        for (int kk = 0; kk < 32; kk += 8) {
            uint32_t a[2][4];
#pragma unroll
            for (int mi = 0; mi < 2; mi++) {
                int r = wm + mi * 16;
                a[mi][0] = f2tf(Ab[(r + g    ) * 40 + kk + c]);
                a[mi][1] = f2tf(Ab[(r + g + 8) * 40 + kk + c]);
                a[mi][2] = f2tf(Ab[(r + g    ) * 40 + kk + c + 4]);
                a[mi][3] = f2tf(Ab[(r + g + 8) * 40 + kk + c + 4]);
            }
#pragma unroll
            for (int j = 0; j < 8; j++) {
                uint32_t b0 = __float_as_uint(Wb[(kk + c    ) * 136 + wn + j * 8 + g]);
                uint32_t b1 = __float_as_uint(Wb[(kk + c + 4) * 136 + wn + j * 8 + g]);
                mma8(acc[0][j], a[0][0], a[0][1], a[0][2], a[0][3], b0, b1);
                mma8(acc[1][j], a[1][0], a[1][1], a[1][2], a[1][3], b0, b1);
            }
        }
        __syncthreads();
        buf ^= 1;
    }

#pragma unroll
    for (int mi = 0; mi < 2; mi++) {
#pragma unroll
        for (int j = 0; j < 8; j++) {
            int r0  = bm + wm + mi * 16 + g;
            int col = bn + wn + j * 8 + (c << 1);
            float bx = bias[col], by = bias[col + 1];
            float2 v0 = { acc[mi][j].x + bx, acc[mi][j].y + by };
            float2 v1 = { acc[mi][j].z + bx, acc[mi][j].w + by };
            if (R) {
                float2 r0v = *(const float2*)(R + (size_t)r0 * N + col);
                float2 r1v = *(const float2*)(R + (size_t)(r0 + 8) * N + col);
                v0.x += r0v.x; v0.y += r0v.y;
                v1.x += r1v.x; v1.y += r1v.y;
            }
            if (round_c) {
                v0.x = rndf(v0.x); v0.y = rndf(v0.y);
                v1.x = rndf(v1.x); v1.y = rndf(v1.y);
            }
            *(float2*)(C + (size_t)r0 * N + col)       = v0;
            *(float2*)(C + (size_t)(r0 + 8) * N + col) = v1;
        }
    }
}

__global__ __launch_bounds__(256, 2) void qkv_gemm(
    const float* q, const float* k, const float* v,
    const float* Wq, const float* Wk, const float* Wv,
    const float* bq, const float* bk, const float* bv,
    float* qh, float* kh, float* vh)
{
    extern __shared__ char sm[];
    int z = blockIdx.z;
    const float* A = z == 0 ? q  : (z == 1 ? k  : v);
    const float* W = z == 0 ? Wq : (z == 1 ? Wk : Wv);
    const float* b = z == 0 ? bq : (z == 1 ? bk : bv);
    float*       C = z == 0 ? qh : (z == 1 ? kh : vh);
    gemm_body(A, W, b, nullptr, C, 1, sm);
}

__global__ __launch_bounds__(256, 2) void oproj_gemm(
    const float* ctx, const float* Wo, const float* bo,
    const float* R, float* C)
{
    extern __shared__ char sm[];
    gemm_body(ctx, Wo, bo, R, C, 0, sm);
}

// ---------------------------------------------------------------------------
// Fused attention, 128q x full-K, 2 passes, tf32 MMA.
// Pair-interleaved smem for Q/K/P (LDS.64 frag loads), straight Vs (pad 72).
// K reg-prefetch; V LDG parked in regs through P-phase.
// smem: Qs[128*72] Ks[64*72] Vs[64*72] Ps[128*72] u32 = 110592 B.
// ---------------------------------------------------------------------------
#define AQS 0
#define AKS (128 * 72)
#define AVS (128 * 72 + 64 * 72)
#define APS (128 * 72 + 64 * 72 + 64 * 72)

__global__ __launch_bounds__(256, 2) void attn_kernel(
    const float* __restrict__ qh, const float* __restrict__ kh,
    const float* __restrict__ vh, const unsigned char* __restrict__ mask,
    float* __restrict__ attn, float* __restrict__ ctx, int write_attn)
{
    extern __shared__ uint32_t smu[];
    uint32_t* Qs = smu + AQS;
    uint32_t* Ks = smu + AKS;
    uint32_t* Vs = smu + AVS;
    uint32_t* Ps = smu + APS;

    const int tid  = threadIdx.x;
    const int lane = tid & 31, wid = tid >> 5;
    const int g = lane >> 2, c = lane & 3;
    const int q0 = blockIdx.x * 128;
    const int bh = blockIdx.y, b = bh >> 4, h = bh & 15;
    const int qw = wid * 16;
    const int c2 = c << 1;
    const int ilv0 = ((c2 & 3) << 1) + (c >> 1);
    const int ilv1 = (((c2 + 1) & 3) << 1) + ((c2 + 1) >> 2);

    // ---- Q tile: load, scale by 0.125 (exact), pair-interleave into smem ----
    const float* qbase = qh + ((size_t)(b * L_ + q0)) * D_ + h * DKV;
#pragma unroll
    for (int u = 0; u < 4; u++) {
        int i = tid + u * 256;
        int r = i >> 3, base = (i & 7) << 3;
        const float* p = qbase + (size_t)r * D_ + base;
        float4 x0 = *(const float4*)p;
        float4 x1 = *(const float4*)(p + 4);
        x0.x *= 0.125f; x0.y *= 0.125f; x0.z *= 0.125f; x0.w *= 0.125f;
        x1.x *= 0.125f; x1.y *= 0.125f; x1.z *= 0.125f; x1.w *= 0.125f;
        uint4 s0 = { __float_as_uint(x0.x), __float_as_uint(x1.x),
                     __float_as_uint(x0.y), __float_as_uint(x1.y) };
        uint4 s1 = { __float_as_uint(x0.z), __float_as_uint(x1.z),
                     __float_as_uint(x0.w), __float_as_uint(x1.w) };
        *(uint4*)&Qs[r * 72 + base]     = s0;
        *(uint4*)&Qs[r * 72 + base + 4] = s1;
    }

    float rk[16], rv[16];
    auto loadK = [&](int kt) {
        const float* kb = kh + ((size_t)(b * L_ + kt)) * D_ + h * DKV;
#pragma unroll
        for (int u = 0; u < 2; u++) {
            int i = tid + u * 256;
            int r = i >> 3, base = (i & 7) << 3;
            *(float4*)&rk[u * 8]     = *(const float4*)(kb + (size_t)r * D_ + base);
            *(float4*)&rk[u * 8 + 4] = *(const float4*)(kb + (size_t)r * D_ + base + 4);
        }
    };
    auto storeK = [&]() {
#pragma unroll
        for (int u = 0; u < 2; u++) {
            int i = tid + u * 256;
            int r = i >> 3, base = (i & 7) << 3;
            const float* e = &rk[u * 8];
            uint4 s0 = { __float_as_uint(e[0]), __float_as_uint(e[4]),
                         __float_as_uint(e[1]), __float_as_uint(e[5]) };
            uint4 s1 = { __float_as_uint(e[2]), __float_as_uint(e[6]),
                         __float_as_uint(e[3]), __float_as_uint(e[7]) };
            *(uint4*)&Ks[r * 72 + base]     = s0;
            *(uint4*)&Ks[r * 72 + base + 4] = s1;
        }
    };
    auto loadV = [&](int kt) {
        const float* vb = vh + ((size_t)(b * L_ + kt)) * D_ + h * DKV;
#pragma unroll
        for (int u = 0; u < 2; u++) {
            int i = tid + u * 256;
            int r = i >> 3, base = (i & 7) << 3;
            *(float4*)&rv[u * 8]     = *(const float4*)(vb + (size_t)r * D_ + base);
            *(float4*)&rv[u * 8 + 4] = *(const float4*)(vb + (size_t)r * D_ + base + 4);
        }
    };
    auto storeV = [&]() {
#pragma unroll
        for (int u = 0; u < 2; u++) {
            int i = tid + u * 256;
            int r = i >> 3, base = (i & 7) << 3;
            *(uint4*)&Vs[r * 72 + base]     = *(uint4*)&rv[u * 8];
            *(uint4*)&Vs[r * 72 + base + 4] = *(uint4*)&rv[u * 8 + 4];
        }
    };

    const int qg0 = q0 + qw + g;
    const int qg1 = qg0 + 8;
    const unsigned char* mbase = mask + (size_t)b * L_ * L_;

    float m0 = -INFINITY, m1 = -INFINITY, l0 = 0.f, l1 = 0.f;

    // ------------------------- PASS 1: stats -------------------------
    loadK(0);
    for (int kt = 0; kt < L_; kt += 64) {
        __syncthreads();
        storeK();
        __syncthreads();
        if (kt + 64 < L_) loadK(kt + 64);

        float4 S[8];
#pragma unroll
        for (int j = 0; j < 8; j++) S[j] = make_float4(0.f, 0.f, 0.f, 0.f);
#pragma unroll
        for (int kk = 0; kk < 64; kk += 8) {
            uint2 a0 = *(uint2*)&Qs[(qw + g    ) * 72 + kk + c2];
            uint2 a1 = *(uint2*)&Qs[(qw + g + 8) * 72 + kk + c2];
#pragma unroll
            for (int j = 0; j < 8; j++) {
                uint2 bb = *(uint2*)&Ks[(j * 8 + g) * 72 + kk + c2];
                mma8(S[j], a0.x, a1.x, a0.y, a1.y, bb.x, bb.y);
            }
        }

        float tm0 = -INFINITY, tm1 = -INFINITY;
#pragma unroll
        for (int j = 0; j < 8; j++) {
            int kcol = kt + j * 8 + c2;
            uchar2 mr0 = *(const uchar2*)(mbase + (size_t)qg0 * L_ + kcol);
            uchar2 mr1 = *(const uchar2*)(mbase + (size_t)qg1 * L_ + kcol);
            if (mr0.x) S[j].x = -INFINITY;
            if (mr0.y) S[j].y = -INFINITY;
            if (mr1.x) S[j].z = -INFINITY;
            if (mr1.y) S[j].w = -INFINITY;
            tm0 = fmaxf(tm0, fmaxf(S[j].x, S[j].y));
            tm1 = fmaxf(tm1, fmaxf(S[j].z, S[j].w));
        }
        tm0 = fmaxf(tm0, __shfl_xor_sync(0xffffffffu, tm0, 1));
        tm0 = fmaxf(tm0, __shfl_xor_sync(0xffffffffu, tm0, 2));
        tm1 = fmaxf(tm1, __shfl_xor_sync(0xffffffffu, tm1, 1));
        tm1 = fmaxf(tm1, __shfl_xor_sync(0xffffffffu, tm1, 2));

        float mn0 = fmaxf(m0, tm0), mn1 = fmaxf(m1, tm1);
        float ts0 = 0.f, ts1 = 0.f;
#pragma unroll
        for (int j = 0; j < 8; j++) {
            ts0 += __expf(S[j].x - mn0) + __expf(S[j].y - mn0);
            ts1 += __expf(S[j].z - mn1) + __expf(S[j].w - mn1);
        }
        ts0 += __shfl_xor_sync(0xffffffffu, ts0, 1);
        ts0 += __shfl_xor_sync(0xffffffffu, ts0, 2);
        ts1 += __shfl_xor_sync(0xffffffffu, ts1, 1);
        ts1 += __shfl_xor_sync(0xffffffffu, ts1, 2);

        l0 = l0 * __expf(m0 - mn0) + ts0;
        l1 = l1 * __expf(m1 - mn1) + ts1;
        m0 = mn0; m1 = mn1;
    }

    // ------------------- PASS 2: attn write + O = P@V -------------------
    const float inv0 = 1.0f / l0;
    const float inv1 = 1.0f / l1;
    float4 O[8];
#pragma unroll
    for (int j = 0; j < 8; j++) O[j] = make_float4(0.f, 0.f, 0.f, 0.f);

    loadK(0);
    for (int kt = 0; kt < L_; kt += 64) {
        __syncthreads();
        storeK();
        __syncthreads();
        if (kt + 64 < L_) loadK(kt + 64);

        float4 S[8];
#pragma unroll
        for (int j = 0; j < 8; j++) S[j] = make_float4(0.f, 0.f, 0.f, 0.f);
#pragma unroll
        for (int kk = 0; kk < 64; kk += 8) {
            uint2 a0 = *(uint2*)&Qs[(qw + g    ) * 72 + kk + c2];
            uint2 a1 = *(uint2*)&Qs[(qw + g + 8) * 72 + kk + c2];
#pragma unroll
            for (int j = 0; j < 8; j++) {
                uint2 bb = *(uint2*)&Ks[(j * 8 + g) * 72 + kk + c2];
                mma8(S[j], a0.x, a1.x, a0.y, a1.y, bb.x, bb.y);
            }
        }

        loadV(kt);   // issue LDGs now; latency hidden behind P-phase

        // P = exp(s - m) / l ; write attn (unrounded), store tf32 P into Ps
#pragma unroll
        for (int j = 0; j < 8; j++) {
            int kcol = kt + j * 8 + c2;
            uchar2 mr0 = *(const uchar2*)(mbase + (size_t)qg0 * L_ + kcol);
            uchar2 mr1 = *(const uchar2*)(mbase + (size_t)qg1 * L_ + kcol);
            float px = mr0.x ? 0.f : __expf(S[j].x - m0) * inv0;
            float py = mr0.y ? 0.f : __expf(S[j].y - m0) * inv0;
            float pz = mr1.x ? 0.f : __expf(S[j].z - m1) * inv1;
            float pw = mr1.y ? 0.f : __expf(S[j].w - m1) * inv1;
            if (write_attn) {
                *(float2*)(attn + ((size_t)bh * L_ + qg0) * L_ + kcol) = make_float2(px, py);
                *(float2*)(attn + ((size_t)bh * L_ + qg1) * L_ + kcol) = make_float2(pz, pw);
            }
            int r0 = (qw + g    ) * 72 + j * 8;
            int r1 = (qw + g + 8) * 72 + j * 8;
            Ps[r0 + ilv0] = f2tf(px);
            Ps[r0 + ilv1] = f2tf(py);
            Ps[r1 + ilv0] = f2tf(pz);
            Ps[r1 + ilv1] = f2tf(pw);
        }
        __syncwarp();

        storeV();
        __syncthreads();

        // O += P @ V
#pragma unroll
        for (int kk = 0; kk < 64; kk += 8) {
            uint2 a0 = *(uint2*)&Ps[(qw + g    ) * 72 + kk + c2];
            uint2 a1 = *(uint2*)&Ps[(qw + g + 8) * 72 + kk + c2];
#pragma unroll
            for (int j = 0; j < 8; j++) {
                uint32_t b0 = Vs[(kk + c    ) * 72 + j * 8 + g];
                uint32_t b1 = Vs[(kk + c + 4) * 72 + j * 8 + g];
                mma8(O[j], a0.x, a1.x, a0.y, a1.y, b0, b1);
            }
        }
    }

    // ctx write (tf32-rounded so O-proj can skip cvt via idempotence)
    float* cb0 = ctx + ((size_t)(b * L_ + qg0)) * D_ + h * DKV;
    float* cb1 = cb0 + (size_t)8 * D_;
#pragma unroll
    for (int j = 0; j < 8; j++) {
        int col = j * 8 + c2;
        *(float2*)(cb0 + col) = make_float2(rndf(O[j].x), rndf(O[j].y));
        *(float2*)(cb1 + col) = make_float2(rndf(O[j].z), rndf(O[j].w));
    }
}

// ---------------------------------------------------------------------------
// LayerNorm over D_=1024
// ---------------------------------------------------------------------------
__device__ __forceinline__ float warp_sum(float v) {
#pragma unroll
    for (int o = 16; o; o >>= 1) v += __shfl_xor_sync(0xffffffffu, v, o);
    return v;
}

__global__ __launch_bounds__(256) void ln_kernel(
    const float* __restrict__ X, const float* __restrict__ gamma,
    const float* __restrict__ beta, float* __restrict__ O)
{
    const float* x = X + (size_t)blockIdx.x * D_;
    const int tid = threadIdx.x;
    __shared__ float rs[8], rq[8];

    float4 v = *(const float4*)(x + tid * 4);
    float s  = v.x + v.y + v.z + v.w;
    float q2 = v.x * v.x + v.y * v.y + v.z * v.z + v.w * v.w;
    s  = warp_sum(s);
    q2 = warp_sum(q2);
    if ((tid & 31) == 0) { rs[tid >> 5] = s; rq[tid >> 5] = q2; }
    __syncthreads();
    float S = 0.f, Q = 0.f;
#pragma unroll
    for (int w = 0; w < 8; w++) { S += rs[w]; Q += rq[w]; }
    float mu  = S * (1.0f / D_);
    float var = Q * (1.0f / D_) - mu * mu;
    float inv = rsqrtf(var + 1e-5f);

    float4 gmm = *(const float4*)(gamma + tid * 4);
    float4 bb  = *(const float4*)(beta + tid * 4);
    float4 o;
    o.x = (v.x - mu) * inv * gmm.x + bb.x;
    o.y = (v.y - mu) * inv * gmm.y + bb.y;
    o.z = (v.z - mu) * inv * gmm.z + bb.z;
    o.w = (v.w - mu) * inv * gmm.w + bb.w;
    *(float4*)(O + (size_t)blockIdx.x * D_ + tid * 4) = o;
}

// ---------------------------------------------------------------------------
// Launch
// ---------------------------------------------------------------------------
extern "C" void kernel_launch(void* const* d_in, const int* in_sizes, int n_in,
                              void* d_out, int out_size)
{
    const float*         q     = (const float*)d_in[0];
    const float*         k     = (const float*)d_in[1];
    const float*         v     = (const float*)d_in[2];
    const unsigned char* mask  = (const unsigned char*)d_in[4];
    const float*         Wq    = (const float*)d_in[5];
    const float*         bq    = (const float*)d_in[6];
    const float*         Wk    = (const float*)d_in[7];
    const float*         bk    = (const float*)d_in[8];
    const float*         Wv    = (const float*)d_in[9];
    const float*         bv    = (const float*)d_in[10];
    const float*         Wo    = (const float*)d_in[11];
    const float*         bo    = (const float*)d_in[12];
    const float*         gamma = (const float*)d_in[13];
    const float*         beta  = (const float*)d_in[14];
    float*               out   = (float*)d_out;

    float *qh, *kh, *vh, *ctx, *xb, *wr;
    cudaGetSymbolAddress((void**)&qh,  g_qh);
    cudaGetSymbolAddress((void**)&kh,  g_kh);
    cudaGetSymbolAddress((void**)&vh,  g_vh);
    cudaGetSymbolAddress((void**)&ctx, g_ctx);
    cudaGetSymbolAddress((void**)&xb,  g_x);
    cudaGetSymbolAddress((void**)&wr,  g_wr);

    const size_t n_out  = (size_t)B_ * L_ * D_;
    const size_t n_attn = (size_t)B_ * H_ * L_ * L_;
    int write_attn = ((size_t)out_size >= n_out + n_attn) ? 1 : 0;
    float* attn = write_attn ? out + n_out : nullptr;

    const int GEMM_SMEM = (2 * 128 * 40 + 2 * 32 * 136) * 4;   // 75776
    const int ATTN_SMEM = (128 * 72 + 64 * 72 + 64 * 72 + 128 * 72) * 4;  // 110592
    cudaFuncSetAttribute(qkv_gemm,   cudaFuncAttributeMaxDynamicSharedMemorySize, GEMM_SMEM);
    cudaFuncSetAttribute(oproj_gemm, cudaFuncAttributeMaxDynamicSharedMemorySize, GEMM_SMEM);
    cudaFuncSetAttribute(attn_kernel, cudaFuncAttributeMaxDynamicSharedMemorySize, ATTN_SMEM);

    // Pre-round weights to tf32 (rounded-once, reused by all tiles)
    const int n4 = (D_ * D_) / 4;
    round_kernel<<<(n4 + 255) / 256, 256>>>((const float4*)Wq, (float4*)(wr + 0 * D_ * D_), n4);
    round_kernel<<<(n4 + 255) / 256, 256>>>((const float4*)Wk, (float4*)(wr + 1 * D_ * D_), n4);
    round_kernel<<<(n4 + 255) / 256, 256>>>((const float4*)Wv, (float4*)(wr + 2 * D_ * D_), n4);
    round_kernel<<<(n4 + 255) / 256, 256>>>((const float4*)Wo, (float4*)(wr + 3 * D_ * D_), n4);

    const int M = B_ * L_;                 // 8192
    dim3 gqkv(D_ / 128, M / 128, 3);       // (8, 64, 3)

    qkv_gemm<<<gqkv, 256, GEMM_SMEM>>>(q, k, v,
        wr + 0 * D_ * D_, wr + 1 * D_ * D_, wr + 2 * D_ * D_,
        bq, bk, bv, qh, kh, vh);

    attn_kernel<<<dim3(L_ / 128, B_ * H_), 256, ATTN_SMEM>>>(qh, kh, vh, mask, attn, ctx, write_attn);

    oproj_gemm<<<dim3(D_ / 128, M / 128), 256, GEMM_SMEM>>>(ctx, wr + 3 * D_ * D_, bo, q, xb);
    ln_kernel<<<M, 256>>>(xb, gamma, beta, out);
}

// round 7
// speedup vs baseline: 2.4922x; 1.1545x over previous
#include <cuda_runtime.h>
#include <math.h>
#include <cstddef>
#include <stdint.h>

#define B_   4
#define L_   2048
#define D_   1024
#define H_   16
#define DKV  64

// ---------------------------------------------------------------------------
// Scratch (allocation-free: __device__ globals)
// ---------------------------------------------------------------------------
static __device__ float g_qh [(size_t)B_ * L_ * D_];
static __device__ float g_kh [(size_t)B_ * L_ * D_];
static __device__ float g_vh [(size_t)B_ * L_ * D_];
static __device__ float g_ctx[(size_t)B_ * L_ * D_];
static __device__ float g_x  [(size_t)B_ * L_ * D_];
static __device__ float g_wr [4 * 1048576];                       // tf32 weights
static __device__ unsigned long long g_mp[(size_t)B_ * L_ * 32];  // packed mask

// ---------------------------------------------------------------------------
// Helpers
// ---------------------------------------------------------------------------
__device__ __forceinline__ uint32_t f2tf(float f) {
    uint32_t u;
    asm("cvt.rna.tf32.f32 %0, %1;" : "=r"(u) : "f"(f));
    return u;
}
__device__ __forceinline__ float rndf(float x) { return __uint_as_float(f2tf(x)); }

__device__ __forceinline__ void mma8(float4& d,
    uint32_t a0, uint32_t a1, uint32_t a2, uint32_t a3,
    uint32_t b0, uint32_t b1)
{
    asm volatile(
        "mma.sync.aligned.m16n8k8.row.col.f32.tf32.tf32.f32 "
        "{%0,%1,%2,%3}, {%4,%5,%6,%7}, {%8,%9}, {%0,%1,%2,%3};"
        : "+f"(d.x), "+f"(d.y), "+f"(d.z), "+f"(d.w)
        : "r"(a0), "r"(a1), "r"(a2), "r"(a3), "r"(b0), "r"(b1));
}

__device__ __forceinline__ void cp16(uint32_t dst, const void* src) {
    asm volatile("cp.async.ca.shared.global [%0], [%1], 16;" :: "r"(dst), "l"(src));
}
__device__ __forceinline__ void cpcommit() { asm volatile("cp.async.commit_group;"); }
__device__ __forceinline__ void cpwait0()  { asm volatile("cp.async.wait_group 0;"); }
__device__ __forceinline__ void cpwait1()  { asm volatile("cp.async.wait_group 1;"); }

// ---------------------------------------------------------------------------
// Weight pre-rounding
// ---------------------------------------------------------------------------
__global__ __launch_bounds__(256) void round_kernel(
    const float4* __restrict__ src, float4* __restrict__ dst, int n4)
{
    int i = blockIdx.x * blockDim.x + threadIdx.x;
    if (i < n4) {
        float4 v = src[i];
        v.x = rndf(v.x); v.y = rndf(v.y); v.z = rndf(v.z); v.w = rndf(v.w);
        dst[i] = v;
    }
}

// ---------------------------------------------------------------------------
// Mask bit-packing: mp[row][w] bit i = mask[row][w*64+i] != 0
// ---------------------------------------------------------------------------
__global__ __launch_bounds__(256) void pack_mask(
    const unsigned char* __restrict__ mask, unsigned long long* __restrict__ mp)
{
    int idx = blockIdx.x * blockDim.x + threadIdx.x;      // (row, word)
    if (idx >= B_ * L_ * 32) return;
    const unsigned* s = (const unsigned*)(mask + (size_t)idx * 64);
    unsigned long long bits = 0;
#pragma unroll
    for (int i = 0; i < 16; i++) {
        unsigned v = __ldg(s + i);
        unsigned t = ((v & 0x000000FFu) ? 1u : 0u)
                   | ((v & 0x0000FF00u) ? 2u : 0u)
                   | ((v & 0x00FF0000u) ? 4u : 0u)
                   | ((v & 0xFF000000u) ? 8u : 0u);
        bits |= (unsigned long long)t << (i * 4);
    }
    mp[idx] = bits;
}

// ---------------------------------------------------------------------------
// GEMM body: C[M=8192, N=1024] = (A @ W + bias (+R)) * cscale, tf32 2-stage.
// ---------------------------------------------------------------------------
__device__ __forceinline__ void gemm_body(
    const float* __restrict__ A, const float* __restrict__ W,
    const float* __restrict__ bias, const float* __restrict__ R,
    float* __restrict__ C, int round_c, float cscale, char* smraw)
{
    float* As = (float*)smraw;                 // 2*128*40
    float* Ws = (float*)smraw + 2 * 128 * 40;  // 2*32*136
    const int tid  = threadIdx.x;
    const int lane = tid & 31, wid = tid >> 5;
    const int wm = (wid & 3) * 32, wn = (wid >> 2) * 64;
    const int g = lane >> 2, c = lane & 3;
    const int bm = blockIdx.y * 128, bn = blockIdx.x * 128;
    const int K = D_, N = D_;

    uint32_t asBase = (uint32_t)__cvta_generic_to_shared(As);
    uint32_t wsBase = (uint32_t)__cvta_generic_to_shared(Ws);

    auto issue = [&](int buf, int kt) {
#pragma unroll
        for (int u = 0; u < 4; u++) {
            int i = tid + u * 256;
            int r = i >> 3, off = (i & 7) << 2;
            cp16(asBase + (uint32_t)(buf * 5120 + r * 40 + off) * 4,
                 A + (size_t)(bm + r) * K + kt + off);
        }
#pragma unroll
        for (int u = 0; u < 4; u++) {
            int i = tid + u * 256;
            int r = i >> 5, off = (i & 31) << 2;
            cp16(wsBase + (uint32_t)(buf * 4352 + r * 136 + off) * 4,
                 W + (size_t)(kt + r) * N + bn + off);
        }
        cpcommit();
    };

    float4 acc[2][8];
#pragma unroll
    for (int mi = 0; mi < 2; mi++)
#pragma unroll
        for (int j = 0; j < 8; j++) acc[mi][j] = make_float4(0.f, 0.f, 0.f, 0.f);

    issue(0, 0);
    int buf = 0;
    for (int kt = 0; kt < K; kt += 32) {
        if (kt + 32 < K) { issue(buf ^ 1, kt + 32); cpwait1(); }
        else             { cpwait0(); }
        __syncthreads();
        const float* Ab = As + buf * 5120;
        const float* Wb = Ws + buf * 4352;
#pragma unroll
        for (int kk = 0; kk < 32; kk += 8) {
            uint32_t a[2][4];
#pragma unroll
            for (int mi = 0; mi < 2; mi++) {
                int r = wm + mi * 16;
                a[mi][0] = f2tf(Ab[(r + g    ) * 40 + kk + c]);
                a[mi][1] = f2tf(Ab[(r + g + 8) * 40 + kk + c]);
                a[mi][2] = f2tf(Ab[(r + g    ) * 40 + kk + c + 4]);
                a[mi][3] = f2tf(Ab[(r + g + 8) * 40 + kk + c + 4]);
            }
#pragma unroll
            for (int j = 0; j < 8; j++) {
                uint32_t b0 = __float_as_uint(Wb[(kk + c    ) * 136 + wn + j * 8 + g]);
                uint32_t b1 = __float_as_uint(Wb[(kk + c + 4) * 136 + wn + j * 8 + g]);
                mma8(acc[0][j], a[0][0], a[0][1], a[0][2], a[0][3], b0, b1);
                mma8(acc[1][j], a[1][0], a[1][1], a[1][2], a[1][3], b0, b1);
            }
        }
        __syncthreads();
        buf ^= 1;
    }

#pragma unroll
    for (int mi = 0; mi < 2; mi++) {
#pragma unroll
        for (int j = 0; j < 8; j++) {
            int r0  = bm + wm + mi * 16 + g;
            int col = bn + wn + j * 8 + (c << 1);
            float bx = bias[col], by = bias[col + 1];
            float2 v0 = { acc[mi][j].x + bx, acc[mi][j].y + by };
            float2 v1 = { acc[mi][j].z + bx, acc[mi][j].w + by };
            if (R) {
                float2 r0v = *(const float2*)(R + (size_t)r0 * N + col);
                float2 r1v = *(const float2*)(R + (size_t)(r0 + 8) * N + col);
                v0.x += r0v.x; v0.y += r0v.y;
                v1.x += r1v.x; v1.y += r1v.y;
            }
            v0.x *= cscale; v0.y *= cscale; v1.x *= cscale; v1.y *= cscale;
            if (round_c) {
                v0.x = rndf(v0.x); v0.y = rndf(v0.y);
                v1.x = rndf(v1.x); v1.y = rndf(v1.y);
            }
            *(float2*)(C + (size_t)r0 * N + col)       = v0;
            *(float2*)(C + (size_t)(r0 + 8) * N + col) = v1;
        }
    }
}

__global__ __launch_bounds__(256, 2) void qkv_gemm(
    const float* q, const float* k, const float* v,
    const float* Wq, const float* Wk, const float* Wv,
    const float* bq, const float* bk, const float* bv,
    float* qh, float* kh, float* vh)
{
    extern __shared__ char sm[];
    int z = blockIdx.z;
    const float* A = z == 0 ? q  : (z == 1 ? k  : v);
    const float* W = z == 0 ? Wq : (z == 1 ? Wk : Wv);
    const float* b = z == 0 ? bq : (z == 1 ? bk : bv);
    float*       C = z == 0 ? qh : (z == 1 ? kh : vh);
    float scale = (z == 0) ? 0.125f : 1.0f;     // fold 1/sqrt(DK) into Q
    gemm_body(A, W, b, nullptr, C, 1, scale, sm);
}

__global__ __launch_bounds__(256, 2) void oproj_gemm(
    const float* ctx, const float* Wo, const float* bo,
    const float* R, float* C)
{
    extern __shared__ char sm[];
    gemm_body(ctx, Wo, bo, R, C, 0, 1.0f, sm);
}

// ---------------------------------------------------------------------------
// Fused attention: 128q block, K tiles of 64, 2 passes.
// Q fragments in registers; K cp.async double-buffered; V single-buffered;
// bit-packed mask. smem (u32): Ks[2][64*68] Vs[64*68] Ps[128*68] = 87040 B.
// ---------------------------------------------------------------------------
#define KTILE_U32 (64 * 68)     // 4352

__global__ __launch_bounds__(256, 2) void attn_kernel(
    const float* __restrict__ qh, const float* __restrict__ kh,
    const float* __restrict__ vh, const unsigned long long* __restrict__ mp,
    float* __restrict__ attn, float* __restrict__ ctx, int write_attn)
{
    extern __shared__ uint32_t smu[];
    uint32_t* Ks = smu;                       // 2 * 4352
    uint32_t* Vs = smu + 2 * KTILE_U32;       // 4352
    uint32_t* Ps = smu + 3 * KTILE_U32;       // 128*68 = 8704

    const int tid  = threadIdx.x;
    const int lane = tid & 31, wid = tid >> 5;
    const int g = lane >> 2, c = lane & 3;
    const int c2 = c << 1;
    const int q0 = blockIdx.x * 128;
    const int bh = blockIdx.y, b = bh >> 4, h = bh & 15;
    const int qw = wid * 16;

    const uint32_t smemB = (uint32_t)__cvta_generic_to_shared(smu);

    // ---- Q fragments in registers (qh pre-scaled by 0.125, tf32-rounded) ----
    uint32_t aq[8][4];
    {
        const float* qb = qh + ((size_t)(b * L_ + q0 + qw)) * D_ + h * DKV;
#pragma unroll
        for (int s = 0; s < 8; s++) {
            aq[s][0] = __float_as_uint(__ldg(qb + (size_t)g       * D_ + s * 8 + c));
            aq[s][1] = __float_as_uint(__ldg(qb + (size_t)(g + 8) * D_ + s * 8 + c));
            aq[s][2] = __float_as_uint(__ldg(qb + (size_t)g       * D_ + s * 8 + c + 4));
            aq[s][3] = __float_as_uint(__ldg(qb + (size_t)(g + 8) * D_ + s * 8 + c + 4));
        }
    }

    auto issueK = [&](int bufi, int kt) {
        const float* kb = kh + ((size_t)(b * L_ + kt)) * D_ + h * DKV;
#pragma unroll
        for (int u = 0; u < 4; u++) {
            int i = tid + u * 256;
            int r = i >> 4, coff = (i & 15) << 2;
            cp16(smemB + (uint32_t)(bufi * KTILE_U32 + r * 68 + coff) * 4,
                 kb + (size_t)r * D_ + coff);
        }
        cpcommit();
    };
    auto issueV = [&](int kt) {
        const float* vb = vh + ((size_t)(b * L_ + kt)) * D_ + h * DKV;
#pragma unroll
        for (int u = 0; u < 4; u++) {
            int i = tid + u * 256;
            int r = i >> 4, coff = (i & 15) << 2;
            cp16(smemB + (uint32_t)(2 * KTILE_U32 + r * 68 + coff) * 4,
                 vb + (size_t)r * D_ + coff);
        }
        cpcommit();
    };

    const int qg0 = q0 + qw + g;
    const int qg1 = qg0 + 8;
    const unsigned long long* mp0 = mp + (size_t)(b * L_ + qg0) * 32;
    const unsigned long long* mp1 = mp + (size_t)(b * L_ + qg1) * 32;

    float m0 = -INFINITY, m1 = -INFINITY, l0 = 0.f, l1 = 0.f;

    // ------------------------- PASS 1: softmax stats -------------------------
    issueK(0, 0);
    int buf = 0;
    for (int kt = 0; kt < L_; kt += 64) {
        cpwait0();
        __syncthreads();
        if (kt + 64 < L_) issueK(buf ^ 1, kt + 64);

        const uint32_t* Kb = Ks + buf * KTILE_U32;
        float4 S[8];
#pragma unroll
        for (int j = 0; j < 8; j++) S[j] = make_float4(0.f, 0.f, 0.f, 0.f);
#pragma unroll
        for (int s = 0; s < 8; s++) {
#pragma unroll
            for (int j = 0; j < 8; j++) {
                uint32_t b0 = Kb[(j * 8 + g) * 68 + s * 8 + c];
                uint32_t b1 = Kb[(j * 8 + g) * 68 + s * 8 + c + 4];
                mma8(S[j], aq[s][0], aq[s][1], aq[s][2], aq[s][3], b0, b1);
            }
        }

        unsigned long long w0 = mp0[kt >> 6], w1 = mp1[kt >> 6];
        if (w0 | w1) {
#pragma unroll
            for (int j = 0; j < 8; j++) {
                int bi = j * 8 + c2;
                if ((w0 >> bi)       & 1) S[j].x = -INFINITY;
                if ((w0 >> (bi + 1)) & 1) S[j].y = -INFINITY;
                if ((w1 >> bi)       & 1) S[j].z = -INFINITY;
                if ((w1 >> (bi + 1)) & 1) S[j].w = -INFINITY;
            }
        }

        float tm0 = -INFINITY, tm1 = -INFINITY;
#pragma unroll
        for (int j = 0; j < 8; j++) {
            tm0 = fmaxf(tm0, fmaxf(S[j].x, S[j].y));
            tm1 = fmaxf(tm1, fmaxf(S[j].z, S[j].w));
        }
        tm0 = fmaxf(tm0, __shfl_xor_sync(0xffffffffu, tm0, 1));
        tm0 = fmaxf(tm0, __shfl_xor_sync(0xffffffffu, tm0, 2));
        tm1 = fmaxf(tm1, __shfl_xor_sync(0xffffffffu, tm1, 1));
        tm1 = fmaxf(tm1, __shfl_xor_sync(0xffffffffu, tm1, 2));

        float mn0 = fmaxf(m0, tm0), mn1 = fmaxf(m1, tm1);
        float ts0 = 0.f, ts1 = 0.f;
#pragma unroll
        for (int j = 0; j < 8; j++) {
            ts0 += __expf(S[j].x - mn0) + __expf(S[j].y - mn0);
            ts1 += __expf(S[j].z - mn1) + __expf(S[j].w - mn1);
        }
        ts0 += __shfl_xor_sync(0xffffffffu, ts0, 1);
        ts0 += __shfl_xor_sync(0xffffffffu, ts0, 2);
        ts1 += __shfl_xor_sync(0xffffffffu, ts1, 1);
        ts1 += __shfl_xor_sync(0xffffffffu, ts1, 2);

        l0 = l0 * __expf(m0 - mn0) + ts0;
        l1 = l1 * __expf(m1 - mn1) + ts1;
        m0 = mn0; m1 = mn1;
        buf ^= 1;
    }

    // ------------------- PASS 2: attn write + O = P@V -------------------
    const float inv0 = 1.0f / l0;
    const float inv1 = 1.0f / l1;
    float4 O[8];
#pragma unroll
    for (int j = 0; j < 8; j++) O[j] = make_float4(0.f, 0.f, 0.f, 0.f);

    issueK(0, 0);        // safe: buf0 last read 2 tiles ago, all warps past barrier
    buf = 0;
    for (int kt = 0; kt < L_; kt += 64) {
        cpwait0();
        __syncthreads();
        issueV(kt);
        int have_next = (kt + 64 < L_);
        if (have_next) issueK(buf ^ 1, kt + 64);

        const uint32_t* Kb = Ks + buf * KTILE_U32;
        float4 S[8];
#pragma unroll
        for (int j = 0; j < 8; j++) S[j] = make_float4(0.f, 0.f, 0.f, 0.f);
#pragma unroll
        for (int s = 0; s < 8; s++) {
#pragma unroll
            for (int j = 0; j < 8; j++) {
                uint32_t b0 = Kb[(j * 8 + g) * 68 + s * 8 + c];
                uint32_t b1 = Kb[(j * 8 + g) * 68 + s * 8 + c + 4];
                mma8(S[j], aq[s][0], aq[s][1], aq[s][2], aq[s][3], b0, b1);
            }
        }

        unsigned long long w0 = mp0[kt >> 6], w1 = mp1[kt >> 6];
        bool anymask = (w0 | w1) != 0ull;
#pragma unroll
        for (int j = 0; j < 8; j++) {
            float px = __expf(S[j].x - m0) * inv0;
            float py = __expf(S[j].y - m0) * inv0;
            float pz = __expf(S[j].z - m1) * inv1;
            float pw = __expf(S[j].w - m1) * inv1;
            if (anymask) {
                int bi = j * 8 + c2;
                if ((w0 >> bi)       & 1) px = 0.f;
                if ((w0 >> (bi + 1)) & 1) py = 0.f;
                if ((w1 >> bi)       & 1) pz = 0.f;
                if ((w1 >> (bi + 1)) & 1) pw = 0.f;
            }
            int kcol = kt + j * 8 + c2;
            if (write_attn) {
                *(float2*)(attn + ((size_t)bh * L_ + qg0) * L_ + kcol) = make_float2(px, py);
                *(float2*)(attn + ((size_t)bh * L_ + qg1) * L_ + kcol) = make_float2(pz, pw);
            }
            uint2 p01 = { f2tf(px), f2tf(py) };
            uint2 p23 = { f2tf(pz), f2tf(pw) };
            *(uint2*)&Ps[(qw + g    ) * 68 + j * 8 + c2] = p01;
            *(uint2*)&Ps[(qw + g + 8) * 68 + j * 8 + c2] = p23;
        }

        if (have_next) cpwait1(); else cpwait0();   // V(kt) complete
        __syncthreads();                            // V + Ps visible

        // O += P @ V
#pragma unroll
        for (int s = 0; s < 8; s++) {
            uint32_t a0 = Ps[(qw + g    ) * 68 + s * 8 + c];
            uint32_t a1 = Ps[(qw + g + 8) * 68 + s * 8 + c];
            uint32_t a2 = Ps[(qw + g    ) * 68 + s * 8 + c + 4];
            uint32_t a3 = Ps[(qw + g + 8) * 68 + s * 8 + c + 4];
#pragma unroll
            for (int j = 0; j < 8; j++) {
                uint32_t b0 = Vs[(s * 8 + c    ) * 68 + j * 8 + g];
                uint32_t b1 = Vs[(s * 8 + c + 4) * 68 + j * 8 + g];
                mma8(O[j], a0, a1, a2, a3, b0, b1);
            }
        }
        buf ^= 1;
    }

    // ctx write (raw f32; O-proj converts to tf32 itself)
    float* cb0 = ctx + ((size_t)(b * L_ + qg0)) * D_ + h * DKV;
    float* cb1 = cb0 + (size_t)8 * D_;
#pragma unroll
    for (int j = 0; j < 8; j++) {
        int col = j * 8 + c2;
        *(float2*)(cb0 + col) = make_float2(O[j].x, O[j].y);
        *(float2*)(cb1 + col) = make_float2(O[j].z, O[j].w);
    }
}

// ---------------------------------------------------------------------------
// LayerNorm over D_=1024
// ---------------------------------------------------------------------------
__device__ __forceinline__ float warp_sum(float v) {
#pragma unroll
    for (int o = 16; o; o >>= 1) v += __shfl_xor_sync(0xffffffffu, v, o);
    return v;
}

__global__ __launch_bounds__(256) void ln_kernel(
    const float* __restrict__ X, const float* __restrict__ gamma,
    const float* __restrict__ beta, float* __restrict__ O)
{
    const float* x = X + (size_t)blockIdx.x * D_;
    const int tid = threadIdx.x;
    __shared__ float rs[8], rq[8];

    float4 v = *(const float4*)(x + tid * 4);
    float s  = v.x + v.y + v.z + v.w;
    float q2 = v.x * v.x + v.y * v.y + v.z * v.z + v.w * v.w;
    s  = warp_sum(s);
    q2 = warp_sum(q2);
    if ((tid & 31) == 0) { rs[tid >> 5] = s; rq[tid >> 5] = q2; }
    __syncthreads();
    float S = 0.f, Q = 0.f;
#pragma unroll
    for (int w = 0; w < 8; w++) { S += rs[w]; Q += rq[w]; }
    float mu  = S * (1.0f / D_);
    float var = Q * (1.0f / D_) - mu * mu;
    float inv = rsqrtf(var + 1e-5f);

    float4 gmm = *(const float4*)(gamma + tid * 4);
    float4 bb  = *(const float4*)(beta + tid * 4);
    float4 o;
    o.x = (v.x - mu) * inv * gmm.x + bb.x;
    o.y = (v.y - mu) * inv * gmm.y + bb.y;
    o.z = (v.z - mu) * inv * gmm.z + bb.z;
    o.w = (v.w - mu) * inv * gmm.w + bb.w;
    *(float4*)(O + (size_t)blockIdx.x * D_ + tid * 4) = o;
}

// ---------------------------------------------------------------------------
// Launch
// ---------------------------------------------------------------------------
extern "C" void kernel_launch(void* const* d_in, const int* in_sizes, int n_in,
                              void* d_out, int out_size)
{
    const float*         q     = (const float*)d_in[0];
    const float*         k     = (const float*)d_in[1];
    const float*         v     = (const float*)d_in[2];
    const unsigned char* mask  = (const unsigned char*)d_in[4];
    const float*         Wq    = (const float*)d_in[5];
    const float*         bq    = (const float*)d_in[6];
    const float*         Wk    = (const float*)d_in[7];
    const float*         bk    = (const float*)d_in[8];
    const float*         Wv    = (const float*)d_in[9];
    const float*         bv    = (const float*)d_in[10];
    const float*         Wo    = (const float*)d_in[11];
    const float*         bo    = (const float*)d_in[12];
    const float*         gamma = (const float*)d_in[13];
    const float*         beta  = (const float*)d_in[14];
    float*               out   = (float*)d_out;

    float *qh, *kh, *vh, *ctx, *xb, *wr;
    unsigned long long* mpck;
    cudaGetSymbolAddress((void**)&qh,   g_qh);
    cudaGetSymbolAddress((void**)&kh,   g_kh);
    cudaGetSymbolAddress((void**)&vh,   g_vh);
    cudaGetSymbolAddress((void**)&ctx,  g_ctx);
    cudaGetSymbolAddress((void**)&xb,   g_x);
    cudaGetSymbolAddress((void**)&wr,   g_wr);
    cudaGetSymbolAddress((void**)&mpck, g_mp);

    const size_t n_out  = (size_t)B_ * L_ * D_;
    const size_t n_attn = (size_t)B_ * H_ * L_ * L_;
    int write_attn = ((size_t)out_size >= n_out + n_attn) ? 1 : 0;
    float* attn = write_attn ? out + n_out : nullptr;

    const int GEMM_SMEM = (2 * 128 * 40 + 2 * 32 * 136) * 4;   // 75776
    const int ATTN_SMEM = (3 * KTILE_U32 + 128 * 68) * 4;      // 87040
    cudaFuncSetAttribute(qkv_gemm,    cudaFuncAttributeMaxDynamicSharedMemorySize, GEMM_SMEM);
    cudaFuncSetAttribute(oproj_gemm,  cudaFuncAttributeMaxDynamicSharedMemorySize, GEMM_SMEM);
    cudaFuncSetAttribute(attn_kernel, cudaFuncAttributeMaxDynamicSharedMemorySize, ATTN_SMEM);

    const int n4 = (D_ * D_) / 4;
    round_kernel<<<(n4 + 255) / 256, 256>>>((const float4*)Wq, (float4*)(wr + 0 * D_ * D_), n4);
    round_kernel<<<(n4 + 255) / 256, 256>>>((const float4*)Wk, (float4*)(wr + 1 * D_ * D_), n4);
    round_kernel<<<(n4 + 255) / 256, 256>>>((const float4*)Wv, (float4*)(wr + 2 * D_ * D_), n4);
    round_kernel<<<(n4 + 255) / 256, 256>>>((const float4*)Wo, (float4*)(wr + 3 * D_ * D_), n4);
    pack_mask<<<(B_ * L_ * 32 + 255) / 256, 256>>>(mask, mpck);

    const int M = B_ * L_;                 // 8192
    dim3 gqkv(D_ / 128, M / 128, 3);

    qkv_gemm<<<gqkv, 256, GEMM_SMEM>>>(q, k, v,
        wr + 0 * D_ * D_, wr + 1 * D_ * D_, wr + 2 * D_ * D_,
        bq, bk, bv, qh, kh, vh);

    attn_kernel<<<dim3(L_ / 128, B_ * H_), 256, ATTN_SMEM>>>(qh, kh, vh, mpck, attn, ctx, write_attn);

    oproj_gemm<<<dim3(D_ / 128, M / 128), 256, GEMM_SMEM>>>(ctx, wr + 3 * D_ * D_, bo, q, xb);
    ln_kernel<<<M, 256>>>(xb, gamma, beta, out);
}